// round 6
// baseline (speedup 1.0000x reference)
#include <cuda_runtime.h>
#include <math_constants.h>

#define BB 64
#define TT 4096
#define QDIM 1024
#define ADIM 256
#define MASK_VAL (-1e30f)

// Scratch (allocation-free rule: device globals)
__device__ float g_pq[BB * ADIM];        // processed query (B, AD)
__device__ float g_energies[BB * TT];    // masked energies (B, T)

__device__ __forceinline__ float tanh_fast(float x) {
    float y;
    asm("tanh.approx.f32 %0, %1;" : "=f"(y) : "f"(x));
    return y;
}

// ---------------------------------------------------------------------------
// Kernel 1: pq[b,d] = dot(query[b,:], Wq[d,:])   (64 x 256, K=1024)
// Tile (8 b x 8 d), grid = 8 x 32 = 256 blocks. Warp w owns one Wq row in
// registers and accumulates all 8 b-rows concurrently (ILP=8).
// NOTE: ncu shows this kernel as ~10 us but that is a --cache-control all
// artifact (pure cold-DRAM fetch of its 1.3 MB); in-graph it runs L2-warm.
// ---------------------------------------------------------------------------
#define PQ_BT 8
__global__ void __launch_bounds__(256) pq_kernel(const float* __restrict__ query,
                                                 const float* __restrict__ Wq) {
    __shared__ float sq[PQ_BT * QDIM];             // 32 KB

    const int lane = threadIdx.x & 31;
    const int warp = threadIdx.x >> 5;             // 0..7
    const int btile = blockIdx.x >> 5;             // 0..7
    const int dtile = blockIdx.x & 31;             // 0..31
    const int b0 = btile * PQ_BT;
    const int d  = dtile * 8 + warp;

    const float4* w4 = reinterpret_cast<const float4*>(Wq + (size_t)d * QDIM);
    float4 w[8];
#pragma unroll
    for (int k = 0; k < 8; ++k) w[k] = w4[lane + 32 * k];

    {
        const float4* qg = reinterpret_cast<const float4*>(query + (size_t)b0 * QDIM);
        float4* sq4 = reinterpret_cast<float4*>(sq);
#pragma unroll
        for (int i = 0; i < 8; ++i)
            sq4[threadIdx.x + 256 * i] = qg[threadIdx.x + 256 * i];
    }
    __syncthreads();

    const float4* sq4 = reinterpret_cast<const float4*>(sq);
    float s[PQ_BT];
#pragma unroll
    for (int bi = 0; bi < PQ_BT; ++bi) s[bi] = 0.f;

#pragma unroll
    for (int k = 0; k < 8; ++k) {
#pragma unroll
        for (int bi = 0; bi < PQ_BT; ++bi) {
            float4 a = sq4[bi * 256 + lane + 32 * k];
            s[bi] += a.x * w[k].x + a.y * w[k].y + a.z * w[k].z + a.w * w[k].w;
        }
    }

#pragma unroll
    for (int off = 16; off > 0; off >>= 1) {
#pragma unroll
        for (int bi = 0; bi < PQ_BT; ++bi)
            s[bi] += __shfl_xor_sync(0xffffffffu, s[bi], off);
    }
    if (lane == 0) {
#pragma unroll
        for (int bi = 0; bi < PQ_BT; ++bi)
            g_pq[(b0 + bi) * ADIM + d] = s[bi];
    }
}

// ---------------------------------------------------------------------------
// Kernel 2: energies[b,t] = sum_d tanh(pq[b,d] + pm[b,t,d]) * v[d]; mask.
// One warp per 16 t-rows. Masked rows (~50%) never touch pm.
// Unmasked rows processed FOUR at a time (8 LDG.128 in flight per warp,
// 4 interleaved tanh/FMA chains, 4 interleaved shfl reductions).
// Tail rows are clamped to i0: duplicate loads hit L1, duplicate stores
// write identical values (deterministic).
// pm read with __ldcs (streaming, 268 MB read-once).
// mask arrives as int32 (harness normalizes bool -> int32).
// ---------------------------------------------------------------------------
#define TPW 16           // t-rows per warp
__global__ void __launch_bounds__(256) energies_kernel(
        const float* __restrict__ pm,
        const int* __restrict__ mask,
        const float* __restrict__ v) {
    const int lane = threadIdx.x & 31;
    const int warp = threadIdx.x >> 5;
    const int gw = blockIdx.x * 8 + warp;          // global warp id
    const int warpsPerB = TT / TPW;                // 256
    const int b = gw / warpsPerB;
    const int t0 = (gw % warpsPerB) * TPW;
    const size_t base = (size_t)b * TT + t0;

    // Mask for the 16 rows: lanes 0..15 load one each.
    const int myMask = (lane < TPW) ? mask[base + lane] : 1;
    const unsigned bits = __ballot_sync(0xffffffffu, (lane < TPW) && (myMask == 0));

    // Masked rows: write MASK_VAL upfront, coalesced.
    if (lane < TPW && myMask)
        g_energies[base + lane] = MASK_VAL;

    const int n = __popc(bits);
    if (n == 0) return;

    // Register-resident pq row and v (8 floats each per lane)
    const float4* pq4 = reinterpret_cast<const float4*>(g_pq + b * ADIM);
    const float4* v4 = reinterpret_cast<const float4*>(v);
    const float4 p0 = pq4[lane], p1 = pq4[lane + 32];
    const float4 v0 = v4[lane], v1 = v4[lane + 32];

    for (int j = 0; j < n; j += 4) {
        const int i0 = __fns(bits, 0, j + 1);
        const bool h1 = (j + 1 < n), h2 = (j + 2 < n), h3 = (j + 3 < n);
        const int i1 = h1 ? __fns(bits, 0, j + 2) : i0;
        const int i2 = h2 ? __fns(bits, 0, j + 3) : i0;
        const int i3 = h3 ? __fns(bits, 0, j + 4) : i0;

        const float4* x0 = reinterpret_cast<const float4*>(pm + (base + i0) * ADIM);
        const float4* x1 = reinterpret_cast<const float4*>(pm + (base + i1) * ADIM);
        const float4* x2 = reinterpret_cast<const float4*>(pm + (base + i2) * ADIM);
        const float4* x3 = reinterpret_cast<const float4*>(pm + (base + i3) * ADIM);

        // 8 independent 128B loads in flight
        float4 a0 = __ldcs(x0 + lane);
        float4 c0 = __ldcs(x0 + lane + 32);
        float4 a1 = __ldcs(x1 + lane);
        float4 c1 = __ldcs(x1 + lane + 32);
        float4 a2 = __ldcs(x2 + lane);
        float4 c2 = __ldcs(x2 + lane + 32);
        float4 a3 = __ldcs(x3 + lane);
        float4 c3 = __ldcs(x3 + lane + 32);

        float s0, s1, s2, s3;
        s0  = tanh_fast(a0.x + p0.x) * v0.x;
        s1  = tanh_fast(a1.x + p0.x) * v0.x;
        s2  = tanh_fast(a2.x + p0.x) * v0.x;
        s3  = tanh_fast(a3.x + p0.x) * v0.x;
        s0 += tanh_fast(a0.y + p0.y) * v0.y;
        s1 += tanh_fast(a1.y + p0.y) * v0.y;
        s2 += tanh_fast(a2.y + p0.y) * v0.y;
        s3 += tanh_fast(a3.y + p0.y) * v0.y;
        s0 += tanh_fast(a0.z + p0.z) * v0.z;
        s1 += tanh_fast(a1.z + p0.z) * v0.z;
        s2 += tanh_fast(a2.z + p0.z) * v0.z;
        s3 += tanh_fast(a3.z + p0.z) * v0.z;
        s0 += tanh_fast(a0.w + p0.w) * v0.w;
        s1 += tanh_fast(a1.w + p0.w) * v0.w;
        s2 += tanh_fast(a2.w + p0.w) * v0.w;
        s3 += tanh_fast(a3.w + p0.w) * v0.w;
        s0 += tanh_fast(c0.x + p1.x) * v1.x;
        s1 += tanh_fast(c1.x + p1.x) * v1.x;
        s2 += tanh_fast(c2.x + p1.x) * v1.x;
        s3 += tanh_fast(c3.x + p1.x) * v1.x;
        s0 += tanh_fast(c0.y + p1.y) * v1.y;
        s1 += tanh_fast(c1.y + p1.y) * v1.y;
        s2 += tanh_fast(c2.y + p1.y) * v1.y;
        s3 += tanh_fast(c3.y + p1.y) * v1.y;
        s0 += tanh_fast(c0.z + p1.z) * v1.z;
        s1 += tanh_fast(c1.z + p1.z) * v1.z;
        s2 += tanh_fast(c2.z + p1.z) * v1.z;
        s3 += tanh_fast(c3.z + p1.z) * v1.z;
        s0 += tanh_fast(c0.w + p1.w) * v1.w;
        s1 += tanh_fast(c1.w + p1.w) * v1.w;
        s2 += tanh_fast(c2.w + p1.w) * v1.w;
        s3 += tanh_fast(c3.w + p1.w) * v1.w;

#pragma unroll
        for (int off = 16; off > 0; off >>= 1) {
            s0 += __shfl_xor_sync(0xffffffffu, s0, off);
            s1 += __shfl_xor_sync(0xffffffffu, s1, off);
            s2 += __shfl_xor_sync(0xffffffffu, s2, off);
            s3 += __shfl_xor_sync(0xffffffffu, s3, off);
        }

        if (lane == 0) {
            g_energies[base + i0] = s0;
            if (h1) g_energies[base + i1] = s1;
            if (h2) g_energies[base + i2] = s2;
            if (h3) g_energies[base + i3] = s3;
        }
    }
}

// ---------------------------------------------------------------------------
// Kernel 3: row softmax over T=4096. One block (1024 thr) per batch row.
// ---------------------------------------------------------------------------
__global__ void __launch_bounds__(1024) softmax_kernel(float* __restrict__ out) {
    const int b = blockIdx.x;
    const int tid = threadIdx.x;
    const int lane = tid & 31;
    const int warp = tid >> 5;
    __shared__ float red[32];
    __shared__ float bcast;

    float e[4];
    float m = -CUDART_INF_F;
#pragma unroll
    for (int i = 0; i < 4; ++i) {
        e[i] = g_energies[(size_t)b * TT + i * 1024 + tid];
        m = fmaxf(m, e[i]);
    }
#pragma unroll
    for (int off = 16; off > 0; off >>= 1)
        m = fmaxf(m, __shfl_xor_sync(0xffffffffu, m, off));
    if (lane == 0) red[warp] = m;
    __syncthreads();
    if (warp == 0) {
        float mm = red[lane];
#pragma unroll
        for (int off = 16; off > 0; off >>= 1)
            mm = fmaxf(mm, __shfl_xor_sync(0xffffffffu, mm, off));
        if (lane == 0) bcast = mm;
    }
    __syncthreads();
    m = bcast;

    float s = 0.f;
#pragma unroll
    for (int i = 0; i < 4; ++i) {
        e[i] = __expf(e[i] - m);
        s += e[i];
    }
#pragma unroll
    for (int off = 16; off > 0; off >>= 1)
        s += __shfl_xor_sync(0xffffffffu, s, off);
    if (lane == 0) red[warp] = s;
    __syncthreads();
    if (warp == 0) {
        float ss = red[lane];
#pragma unroll
        for (int off = 16; off > 0; off >>= 1)
            ss += __shfl_xor_sync(0xffffffffu, ss, off);
        if (lane == 0) bcast = ss;
    }
    __syncthreads();
    const float inv = 1.0f / bcast;

#pragma unroll
    for (int i = 0; i < 4; ++i)
        out[(size_t)b * TT + i * 1024 + tid] = e[i] * inv;
}

// ---------------------------------------------------------------------------
extern "C" void kernel_launch(void* const* d_in, const int* in_sizes, int n_in,
                              void* d_out, int out_size) {
    const float* query = (const float*)d_in[0];          // (64, 1024) f32
    const float* pm    = (const float*)d_in[1];          // (64, 4096, 256) f32
    const int*   mask  = (const int*)d_in[2];            // (64, 4096) bool -> int32
    const float* Wq    = (const float*)d_in[3];          // (256, 1024) f32
    const float* v     = (const float*)d_in[4];          // (256,) f32
    float* out = (float*)d_out;                          // (64, 4096) f32

    // K1: (8 b-tiles) x (32 d-tiles) = 256 blocks, 256 threads
    pq_kernel<<<256, 256>>>(query, Wq);
    // K2: 64*4096/16 warps / 8 per block = 2048 blocks
    energies_kernel<<<2048, 256>>>(pm, mask, v);
    // K3: one block per batch row
    softmax_kernel<<<BB, 1024>>>(out);
}

// round 7
// speedup vs baseline: 1.2089x; 1.2089x over previous
#include <cuda_runtime.h>
#include <math_constants.h>

#define BB 64
#define TT 4096
#define QDIM 1024
#define ADIM 256
#define MASK_VAL (-1e30f)

// Scratch (allocation-free rule: device globals)
__device__ float g_pq[BB * ADIM];        // processed query (B, AD)
__device__ float g_energies[BB * TT];    // masked energies (B, T)

__device__ __forceinline__ float tanh_fast(float x) {
    float y;
    asm("tanh.approx.f32 %0, %1;" : "=f"(y) : "f"(x));
    return y;
}

// ---------------------------------------------------------------------------
// Kernel 1: pq[b,d] = dot(query[b,:], Wq[d,:])   (64 x 256, K=1024)
// Tile (8 b x 8 d), grid = 256 blocks. Warp w owns one Wq row in registers
// and accumulates all 8 b-rows concurrently (ILP=8).
// (ncu dur for this kernel is a --cache-control all cold-DRAM artifact.)
// ---------------------------------------------------------------------------
#define PQ_BT 8
__global__ void __launch_bounds__(256) pq_kernel(const float* __restrict__ query,
                                                 const float* __restrict__ Wq) {
    __shared__ float sq[PQ_BT * QDIM];             // 32 KB

    const int lane = threadIdx.x & 31;
    const int warp = threadIdx.x >> 5;             // 0..7
    const int btile = blockIdx.x >> 5;             // 0..7
    const int dtile = blockIdx.x & 31;             // 0..31
    const int b0 = btile * PQ_BT;
    const int d  = dtile * 8 + warp;

    const float4* w4 = reinterpret_cast<const float4*>(Wq + (size_t)d * QDIM);
    float4 w[8];
#pragma unroll
    for (int k = 0; k < 8; ++k) w[k] = w4[lane + 32 * k];

    {
        const float4* qg = reinterpret_cast<const float4*>(query + (size_t)b0 * QDIM);
        float4* sq4 = reinterpret_cast<float4*>(sq);
#pragma unroll
        for (int i = 0; i < 8; ++i)
            sq4[threadIdx.x + 256 * i] = qg[threadIdx.x + 256 * i];
    }
    __syncthreads();

    const float4* sq4 = reinterpret_cast<const float4*>(sq);
    float s[PQ_BT];
#pragma unroll
    for (int bi = 0; bi < PQ_BT; ++bi) s[bi] = 0.f;

#pragma unroll
    for (int k = 0; k < 8; ++k) {
#pragma unroll
        for (int bi = 0; bi < PQ_BT; ++bi) {
            float4 a = sq4[bi * 256 + lane + 32 * k];
            s[bi] += a.x * w[k].x + a.y * w[k].y + a.z * w[k].z + a.w * w[k].w;
        }
    }

#pragma unroll
    for (int off = 16; off > 0; off >>= 1) {
#pragma unroll
        for (int bi = 0; bi < PQ_BT; ++bi)
            s[bi] += __shfl_xor_sync(0xffffffffu, s[bi], off);
    }
    if (lane == 0) {
#pragma unroll
        for (int bi = 0; bi < PQ_BT; ++bi)
            g_pq[(b0 + bi) * ADIM + d] = s[bi];
    }
}

// ---------------------------------------------------------------------------
// Kernel 2: energies[b,t] = sum_d tanh(pq[b,d] + pm[b,t,d]) * v[d]; mask.
// One warp per 16 t-rows; masked rows (~50%) never touch pm.
// TWO rows per iteration (tail waste only 0.5 rows avg), SOFTWARE-PIPELINED:
// iteration j+1's four LDG.128 are issued before iteration j's shfl-reduce
// chain, keeping ~8 loads in flight at steady state without the 4-wide
// duplicate-tail tax that regressed R6.
// pm read with __ldcs (streaming, read-once).
// mask arrives as int32 (harness normalizes bool -> int32).
// ---------------------------------------------------------------------------
#define TPW 16           // t-rows per warp
__global__ void __launch_bounds__(256) energies_kernel(
        const float* __restrict__ pm,
        const int* __restrict__ mask,
        const float* __restrict__ v) {
    const int lane = threadIdx.x & 31;
    const int warp = threadIdx.x >> 5;
    const int gw = blockIdx.x * 8 + warp;          // global warp id
    const int warpsPerB = TT / TPW;                // 256
    const int b = gw / warpsPerB;
    const int t0 = (gw % warpsPerB) * TPW;
    const size_t base = (size_t)b * TT + t0;

    // Mask for the 16 rows: lanes 0..15 load one each.
    const int myMask = (lane < TPW) ? mask[base + lane] : 1;
    const unsigned bits = __ballot_sync(0xffffffffu, (lane < TPW) && (myMask == 0));

    // Masked rows: write MASK_VAL upfront, coalesced.
    if (lane < TPW && myMask)
        g_energies[base + lane] = MASK_VAL;

    const int n = __popc(bits);
    if (n == 0) return;

    // Register-resident pq row and v (8 floats each per lane)
    const float4* pq4 = reinterpret_cast<const float4*>(g_pq + b * ADIM);
    const float4* v4 = reinterpret_cast<const float4*>(v);
    const float4 p0 = pq4[lane], p1 = pq4[lane + 32];
    const float4 v0 = v4[lane], v1 = v4[lane + 32];

    const int nIter = (n + 1) >> 1;

    // Prologue: issue loads for iteration 0.
    int i0 = __fns(bits, 0, 1);
    int i1 = (n > 1) ? __fns(bits, 0, 2) : i0;
    const float4* x0 = reinterpret_cast<const float4*>(pm + (base + i0) * ADIM);
    const float4* x1 = reinterpret_cast<const float4*>(pm + (base + i1) * ADIM);
    float4 a0 = __ldcs(x0 + lane);
    float4 c0 = __ldcs(x0 + lane + 32);
    float4 a1 = __ldcs(x1 + lane);
    float4 c1 = __ldcs(x1 + lane + 32);

    for (int it = 0; it < nIter; ++it) {
        const int j = it * 2;
        const bool has1 = (j + 1 < n);
        const int ci0 = i0, ci1 = i1;
        const float4 A0 = a0, C0 = c0, A1 = a1, C1 = c1;

        // Prefetch next pair before the reduce chain of the current pair.
        if (it + 1 < nIter) {
            const int jn = j + 2;
            i0 = __fns(bits, 0, jn + 1);
            i1 = (jn + 1 < n) ? __fns(bits, 0, jn + 2) : i0;
            const float4* y0 = reinterpret_cast<const float4*>(pm + (base + i0) * ADIM);
            const float4* y1 = reinterpret_cast<const float4*>(pm + (base + i1) * ADIM);
            a0 = __ldcs(y0 + lane);
            c0 = __ldcs(y0 + lane + 32);
            a1 = __ldcs(y1 + lane);
            c1 = __ldcs(y1 + lane + 32);
        }

        float s0, s1;
        s0  = tanh_fast(A0.x + p0.x) * v0.x;
        s1  = tanh_fast(A1.x + p0.x) * v0.x;
        s0 += tanh_fast(A0.y + p0.y) * v0.y;
        s1 += tanh_fast(A1.y + p0.y) * v0.y;
        s0 += tanh_fast(A0.z + p0.z) * v0.z;
        s1 += tanh_fast(A1.z + p0.z) * v0.z;
        s0 += tanh_fast(A0.w + p0.w) * v0.w;
        s1 += tanh_fast(A1.w + p0.w) * v0.w;
        s0 += tanh_fast(C0.x + p1.x) * v1.x;
        s1 += tanh_fast(C1.x + p1.x) * v1.x;
        s0 += tanh_fast(C0.y + p1.y) * v1.y;
        s1 += tanh_fast(C1.y + p1.y) * v1.y;
        s0 += tanh_fast(C0.z + p1.z) * v1.z;
        s1 += tanh_fast(C1.z + p1.z) * v1.z;
        s0 += tanh_fast(C0.w + p1.w) * v1.w;
        s1 += tanh_fast(C1.w + p1.w) * v1.w;

#pragma unroll
        for (int off = 16; off > 0; off >>= 1) {
            s0 += __shfl_xor_sync(0xffffffffu, s0, off);
            s1 += __shfl_xor_sync(0xffffffffu, s1, off);
        }

        if (lane == 0) {
            g_energies[base + ci0] = s0;
            if (has1) g_energies[base + ci1] = s1;
        }
    }
}

// ---------------------------------------------------------------------------
// Kernel 3: row softmax over T=4096. One block (1024 thr) per batch row.
// ---------------------------------------------------------------------------
__global__ void __launch_bounds__(1024) softmax_kernel(float* __restrict__ out) {
    const int b = blockIdx.x;
    const int tid = threadIdx.x;
    const int lane = tid & 31;
    const int warp = tid >> 5;
    __shared__ float red[32];
    __shared__ float bcast;

    float e[4];
    float m = -CUDART_INF_F;
#pragma unroll
    for (int i = 0; i < 4; ++i) {
        e[i] = g_energies[(size_t)b * TT + i * 1024 + tid];
        m = fmaxf(m, e[i]);
    }
#pragma unroll
    for (int off = 16; off > 0; off >>= 1)
        m = fmaxf(m, __shfl_xor_sync(0xffffffffu, m, off));
    if (lane == 0) red[warp] = m;
    __syncthreads();
    if (warp == 0) {
        float mm = red[lane];
#pragma unroll
        for (int off = 16; off > 0; off >>= 1)
            mm = fmaxf(mm, __shfl_xor_sync(0xffffffffu, mm, off));
        if (lane == 0) bcast = mm;
    }
    __syncthreads();
    m = bcast;

    float s = 0.f;
#pragma unroll
    for (int i = 0; i < 4; ++i) {
        e[i] = __expf(e[i] - m);
        s += e[i];
    }
#pragma unroll
    for (int off = 16; off > 0; off >>= 1)
        s += __shfl_xor_sync(0xffffffffu, s, off);
    if (lane == 0) red[warp] = s;
    __syncthreads();
    if (warp == 0) {
        float ss = red[lane];
#pragma unroll
        for (int off = 16; off > 0; off >>= 1)
            ss += __shfl_xor_sync(0xffffffffu, ss, off);
        if (lane == 0) bcast = ss;
    }
    __syncthreads();
    const float inv = 1.0f / bcast;

#pragma unroll
    for (int i = 0; i < 4; ++i)
        out[(size_t)b * TT + i * 1024 + tid] = e[i] * inv;
}

// ---------------------------------------------------------------------------
extern "C" void kernel_launch(void* const* d_in, const int* in_sizes, int n_in,
                              void* d_out, int out_size) {
    const float* query = (const float*)d_in[0];          // (64, 1024) f32
    const float* pm    = (const float*)d_in[1];          // (64, 4096, 256) f32
    const int*   mask  = (const int*)d_in[2];            // (64, 4096) bool -> int32
    const float* Wq    = (const float*)d_in[3];          // (256, 1024) f32
    const float* v     = (const float*)d_in[4];          // (256,) f32
    float* out = (float*)d_out;                          // (64, 4096) f32

    // K1: (8 b-tiles) x (32 d-tiles) = 256 blocks, 256 threads
    pq_kernel<<<256, 256>>>(query, Wq);
    // K2: 64*4096/16 warps / 8 per block = 2048 blocks
    energies_kernel<<<2048, 256>>>(pm, mask, v);
    // K3: one block per batch row
    softmax_kernel<<<BB, 1024>>>(out);
}